// round 6
// baseline (speedup 1.0000x reference)
#include <cuda_runtime.h>

#define N_NODES 100000
#define E_EDGES 1600000
#define HDIM 48
#define NQ (HDIM / 4)   // 12 float4 columns
#define CAP 96          // max tracked in-degree (Poisson(16): P(>50) ~ 1e-11)

#define TM 128          // node tile per block
#define SXS 132         // padded shared tile stride (128 + 4)
#define THR 192         // 16 M-tiles x 12 N-tiles

// Persistent scratch (no allocations allowed). Double-buffered features:
// conv k reads one buffer (neighbors live anywhere) and writes the other.
__device__ float g_hA[N_NODES * HDIM];
__device__ float g_hB[N_NODES * HDIM];
__device__ int   g_count[N_NODES];
__device__ int   g_slots[N_NODES * CAP];

// ---------------------------------------------------------------------------
// init: hA = x ; count = 0
// ---------------------------------------------------------------------------
__global__ void init_kernel(const float* __restrict__ x) {
    int i = blockIdx.x * blockDim.x + threadIdx.x;
    if (i < N_NODES * NQ) ((float4*)g_hA)[i] = ((const float4*)x)[i];
    if (i < N_NODES) g_count[i] = 0;
}

// ---------------------------------------------------------------------------
// build adjacency: bin src indices by dst. One int atomic per edge.
// ---------------------------------------------------------------------------
__global__ void build_kernel(const int* __restrict__ ei) {
    int e = blockIdx.x * blockDim.x + threadIdx.x;
    if (e >= E_EDGES) return;
    int src = ei[e];
    int dst = ei[E_EDGES + e];
    int pos = atomicAdd(&g_count[dst], 1);
    if (pos < CAP) g_slots[dst * CAP + pos] = src;
}

// ---------------------------------------------------------------------------
// Gather a 128-node tile (self + neighbor sum) directly into the transposed
// shared tile sT[feat][node]. Thread item = (node m, float4-col c); the 12
// threads of one node read consecutive float4s of each neighbor row
// (coalesced 192B bursts, L2-resident).
// ---------------------------------------------------------------------------
template <bool SRC_A>
__device__ __forceinline__ void gather_tile(float* sT, int tid, int base) {
    const float4* __restrict__ h4 = (const float4*)(SRC_A ? g_hA : g_hB);
    for (int i = tid; i < TM * NQ; i += THR) {
        int c = i % NQ;
        int m = i / NQ;
        int node = base + m;
        float4 acc = make_float4(0.f, 0.f, 0.f, 0.f);
        if (node < N_NODES) {
            acc = h4[node * NQ + c];                       // self (eps=0 GIN)
            int deg = min(g_count[node], CAP);
            const int* __restrict__ sl = g_slots + node * CAP;
            int j = 0;
            for (; j + 4 <= deg; j += 4) {
                int s0 = sl[j], s1 = sl[j + 1], s2 = sl[j + 2], s3 = sl[j + 3];
                float4 v0 = h4[s0 * NQ + c];
                float4 v1 = h4[s1 * NQ + c];
                float4 v2 = h4[s2 * NQ + c];
                float4 v3 = h4[s3 * NQ + c];
                acc.x += (v0.x + v1.x) + (v2.x + v3.x);
                acc.y += (v0.y + v1.y) + (v2.y + v3.y);
                acc.z += (v0.z + v1.z) + (v2.z + v3.z);
                acc.w += (v0.w + v1.w) + (v2.w + v3.w);
            }
            for (; j < deg; j++) {
                int s = sl[j];
                float4 v = h4[s * NQ + c];
                acc.x += v.x; acc.y += v.y; acc.z += v.z; acc.w += v.w;
            }
        }
        sT[(4 * c + 0) * SXS + m] = acc.x;
        sT[(4 * c + 1) * SXS + m] = acc.y;
        sT[(4 * c + 2) * SXS + m] = acc.z;
        sT[(4 * c + 3) * SXS + m] = acc.w;
    }
    __syncthreads();
}

// ---------------------------------------------------------------------------
// 48->48 layer, result back into sT. Thread (mt=tid/12, nt=tid%12) computes
// an 8M x 4N micro-tile: 32 FFMA per (2 LDS.128 + 1 LDG.128).
// ---------------------------------------------------------------------------
__device__ __forceinline__ void layer48_to_smem(
    float* sT, const float* __restrict__ W, const float* __restrict__ B,
    int tid, bool relu) {
    int mt = tid / 12, nt = tid % 12;
    int m0 = mt * 8;
    const float4* __restrict__ W4 = (const float4*)W;
    float4 bias = ((const float4*)B)[nt];

    float acc[8][4];
#pragma unroll
    for (int m = 0; m < 8; m++) {
        acc[m][0] = bias.x; acc[m][1] = bias.y;
        acc[m][2] = bias.z; acc[m][3] = bias.w;
    }
#pragma unroll 8
    for (int k = 0; k < HDIM; k++) {
        float4 b4 = W4[k * NQ + nt];
        float4 a0 = *(const float4*)&sT[k * SXS + m0];
        float4 a1 = *(const float4*)&sT[k * SXS + m0 + 4];
        float a[8] = {a0.x, a0.y, a0.z, a0.w, a1.x, a1.y, a1.z, a1.w};
#pragma unroll
        for (int m = 0; m < 8; m++) {
            acc[m][0] += a[m] * b4.x;
            acc[m][1] += a[m] * b4.y;
            acc[m][2] += a[m] * b4.z;
            acc[m][3] += a[m] * b4.w;
        }
    }
    __syncthreads();   // all reads of sT complete before overwriting
#pragma unroll
    for (int n = 0; n < 4; n++) {
        float4 lo = make_float4(acc[0][n], acc[1][n], acc[2][n], acc[3][n]);
        float4 hi = make_float4(acc[4][n], acc[5][n], acc[6][n], acc[7][n]);
        if (relu) {
            lo.x = fmaxf(lo.x, 0.f); lo.y = fmaxf(lo.y, 0.f);
            lo.z = fmaxf(lo.z, 0.f); lo.w = fmaxf(lo.w, 0.f);
            hi.x = fmaxf(hi.x, 0.f); hi.y = fmaxf(hi.y, 0.f);
            hi.z = fmaxf(hi.z, 0.f); hi.w = fmaxf(hi.w, 0.f);
        }
        int row = nt * 4 + n;
        *(float4*)&sT[row * SXS + m0]     = lo;
        *(float4*)&sT[row * SXS + m0 + 4] = hi;
    }
    __syncthreads();
}

// 48 -> 48 layer writing straight to global gout[node*48 + f] (with relu).
__device__ __forceinline__ void layer48_to_gmem(
    const float* sT, const float* __restrict__ W, const float* __restrict__ B,
    int tid, int base, float* __restrict__ gout, bool relu) {
    int mt = tid / 12, nt = tid % 12;
    int m0 = mt * 8;
    const float4* __restrict__ W4 = (const float4*)W;
    float4 bias = ((const float4*)B)[nt];

    float acc[8][4];
#pragma unroll
    for (int m = 0; m < 8; m++) {
        acc[m][0] = bias.x; acc[m][1] = bias.y;
        acc[m][2] = bias.z; acc[m][3] = bias.w;
    }
#pragma unroll 8
    for (int k = 0; k < HDIM; k++) {
        float4 b4 = W4[k * NQ + nt];
        float4 a0 = *(const float4*)&sT[k * SXS + m0];
        float4 a1 = *(const float4*)&sT[k * SXS + m0 + 4];
        float a[8] = {a0.x, a0.y, a0.z, a0.w, a1.x, a1.y, a1.z, a1.w};
#pragma unroll
        for (int m = 0; m < 8; m++) {
            acc[m][0] += a[m] * b4.x;
            acc[m][1] += a[m] * b4.y;
            acc[m][2] += a[m] * b4.z;
            acc[m][3] += a[m] * b4.w;
        }
    }
#pragma unroll
    for (int m = 0; m < 8; m++) {
        int node = base + m0 + m;
        if (node < N_NODES) {
            float4 v = make_float4(acc[m][0], acc[m][1], acc[m][2], acc[m][3]);
            if (relu) {
                v.x = fmaxf(v.x, 0.f); v.y = fmaxf(v.y, 0.f);
                v.z = fmaxf(v.z, 0.f); v.w = fmaxf(v.w, 0.f);
            }
            *(float4*)&gout[node * HDIM + nt * 4] = v;
        }
    }
}

// 48 -> 16 layer writing to global out[node*16 + f] (no relu). 128 active thr.
__device__ __forceinline__ void layer16_to_gmem(
    const float* sT, const float* __restrict__ W, const float* __restrict__ B,
    int tid, int base, float* __restrict__ out) {
    int mt = tid / 4, nt = tid % 4;
    if (mt >= 32) return;
    int m0 = mt * 4;
    const float4* __restrict__ W4 = (const float4*)W;   // [48][4 float4 cols]
    float4 bias = ((const float4*)B)[nt];

    float acc[4][4];
#pragma unroll
    for (int m = 0; m < 4; m++) {
        acc[m][0] = bias.x; acc[m][1] = bias.y;
        acc[m][2] = bias.z; acc[m][3] = bias.w;
    }
#pragma unroll 8
    for (int k = 0; k < HDIM; k++) {
        float4 b4 = W4[k * 4 + nt];
        float4 a0 = *(const float4*)&sT[k * SXS + m0];
        float a[4] = {a0.x, a0.y, a0.z, a0.w};
#pragma unroll
        for (int m = 0; m < 4; m++) {
            acc[m][0] += a[m] * b4.x;
            acc[m][1] += a[m] * b4.y;
            acc[m][2] += a[m] * b4.z;
            acc[m][3] += a[m] * b4.w;
        }
    }
#pragma unroll
    for (int m = 0; m < 4; m++) {
        int node = base + m0 + m;
        if (node < N_NODES) {
            float4 v = make_float4(acc[m][0], acc[m][1], acc[m][2], acc[m][3]);
            *(float4*)&out[node * 16 + nt * 4] = v;
        }
    }
}

// ---------------------------------------------------------------------------
// Fused conv: gather tile -> relu(W1) -> relu(W2) -> opposite h buffer.
// Blocks in different phases overlap L2 traffic with FFMA work on each SM.
// ---------------------------------------------------------------------------
template <bool SRC_A>
__global__ __launch_bounds__(THR) void conv_fused_kernel(
    const float* __restrict__ W1, const float* __restrict__ b1,
    const float* __restrict__ W2, const float* __restrict__ b2) {
    __shared__ float sT[HDIM * SXS];
    int tid = threadIdx.x;
    int base = blockIdx.x * TM;
    gather_tile<SRC_A>(sT, tid, base);
    layer48_to_smem(sT, W1, b1, tid, true);
    layer48_to_gmem(sT, W2, b2, tid, base, SRC_A ? g_hB : g_hA, true);
}

// ---------------------------------------------------------------------------
// Fused final: gather + conv3 MLP + fc head (4 layers) -> d_out.
// ---------------------------------------------------------------------------
__global__ __launch_bounds__(THR) void final_fused_kernel(
    const float* __restrict__ W1, const float* __restrict__ b1,
    const float* __restrict__ W2, const float* __restrict__ b2,
    const float* __restrict__ W3, const float* __restrict__ b3,
    const float* __restrict__ W4, const float* __restrict__ b4,
    float* __restrict__ out) {
    __shared__ float sT[HDIM * SXS];
    int tid = threadIdx.x;
    int base = blockIdx.x * TM;
    gather_tile<true>(sT, tid, base);          // conv3 reads g_hA
    layer48_to_smem(sT, W1, b1, tid, true);    // conv3 layer 1
    layer48_to_smem(sT, W2, b2, tid, true);    // conv3 layer 2
    layer48_to_smem(sT, W3, b3, tid, true);    // fc1 + relu
    layer16_to_gmem(sT, W4, b4, tid, base, out);  // fc2 -> out
}

// ---------------------------------------------------------------------------
extern "C" void kernel_launch(void* const* d_in, const int* in_sizes, int n_in,
                              void* d_out, int out_size) {
    const float* x   = (const float*)d_in[0];
    const int*   ei  = (const int*)d_in[1];
    const float* w11 = (const float*)d_in[2];
    const float* b11 = (const float*)d_in[3];
    const float* w12 = (const float*)d_in[4];
    const float* b12 = (const float*)d_in[5];
    const float* w21 = (const float*)d_in[6];
    const float* b21 = (const float*)d_in[7];
    const float* w22 = (const float*)d_in[8];
    const float* b22 = (const float*)d_in[9];
    const float* w31 = (const float*)d_in[10];
    const float* b31 = (const float*)d_in[11];
    const float* w32 = (const float*)d_in[12];
    const float* b32 = (const float*)d_in[13];
    const float* wf1 = (const float*)d_in[14];
    const float* bf1 = (const float*)d_in[15];
    const float* wf2 = (const float*)d_in[16];
    const float* bf2 = (const float*)d_in[17];
    float* out = (float*)d_out;

    const int TPB = 256;
    const int init_grid  = (N_NODES * NQ + TPB - 1) / TPB;
    const int build_grid = (E_EDGES + TPB - 1) / TPB;
    const int mlp_grid   = (N_NODES + TM - 1) / TM;

    init_kernel<<<init_grid, TPB>>>(x);
    build_kernel<<<build_grid, TPB>>>(ei);   // adjacency built ONCE, reused x3

    // Conv 1: read A, write B
    conv_fused_kernel<true><<<mlp_grid, THR>>>(w11, b11, w12, b12);
    // Conv 2: read B, write A
    conv_fused_kernel<false><<<mlp_grid, THR>>>(w21, b21, w22, b22);
    // Conv 3 + head fused: read A, write d_out
    final_fused_kernel<<<mlp_grid, THR>>>(w31, b31, w32, b32,
                                          wf1, bf1, wf2, bf2, out);

    (void)in_sizes; (void)n_in; (void)out_size;
}